// round 2
// baseline (speedup 1.0000x reference)
#include <cuda_runtime.h>
#include <cuda_bf16.h>
#include <math.h>

#define N_NODES 100000
#define FMAX 128

// Scratch (static __device__ arrays — no allocation allowed)
__device__ float g_hs  [(size_t)N_NODES * FMAX];
__device__ float g_aggA[(size_t)N_NODES * FMAX];
__device__ float g_aggB[(size_t)N_NODES * FMAX];
__device__ float g_dinv[N_NODES];
__device__ int   g_deg [N_NODES];

// ---------------------------------------------------------------------------
// Degree kernels
// ---------------------------------------------------------------------------
__global__ void zero_deg_kernel(int* __restrict__ deg, int n) {
    int i = blockIdx.x * blockDim.x + threadIdx.x;
    if (i < n) deg[i] = 0;
}

__global__ void count_deg_kernel(const int* __restrict__ ei,
                                 int* __restrict__ deg, long long E) {
    long long i = (long long)blockIdx.x * blockDim.x + threadIdx.x;
    if (i < E) atomicAdd(&deg[ei[E + i]], 1);
}

__global__ void dinv_kernel(const int* __restrict__ deg,
                            float* __restrict__ dinv, int n) {
    int i = blockIdx.x * blockDim.x + threadIdx.x;
    if (i < n) dinv[i] = rsqrtf((float)deg[i] + 1.0f);
}

// ---------------------------------------------------------------------------
// Fused GEMM: reads IN (raw x if FIRST, else prev agg with fused finalize
// relu(dinv*agg + b_prev)), computes hs = (X @ W) * dinv, writes hs and also
// initializes agg := hs (the self-loop term).
// ---------------------------------------------------------------------------
template <int Fin, int Fout, bool FIRST>
__global__ void gemm_fused_kernel(const float* __restrict__ in,
                                  const float* __restrict__ W,
                                  const float* __restrict__ b_prev,
                                  const float* __restrict__ dinv,
                                  float* __restrict__ hs,
                                  float* __restrict__ agg,
                                  int N) {
    constexpr int JT   = Fout / 4;      // float4 chunks per row
    constexpr int ROWS = 256 / JT;      // rows per block
    __shared__ __align__(16) float Ws[Fin * Fout];
    __shared__ float Xs[ROWS * Fin];
    __shared__ float bs[Fin];

    const int tid = threadIdx.x;
    for (int i = tid; i < Fin * Fout; i += 256) Ws[i] = W[i];
    if (!FIRST) {
        for (int i = tid; i < Fin; i += 256) bs[i] = b_prev[i];
    }
    __syncthreads();

    const int row0 = blockIdx.x * ROWS;
    for (int i = tid; i < ROWS * Fin; i += 256) {
        int r = row0 + i / Fin;
        int k = i % Fin;
        float v = 0.f;
        if (r < N) {
            v = in[(size_t)r * Fin + k];
            if (!FIRST) v = fmaxf(fmaf(dinv[r], v, bs[k]), 0.f);
        }
        Xs[i] = v;
    }
    __syncthreads();

    const int tj = tid % JT;
    const int tr = tid / JT;
    const int r  = row0 + tr;
    if (r >= N) return;

    float4 acc = make_float4(0.f, 0.f, 0.f, 0.f);
    const float4* W4 = reinterpret_cast<const float4*>(Ws);
    const float* xrow = &Xs[tr * Fin];
#pragma unroll 8
    for (int k = 0; k < Fin; k++) {
        float  x = xrow[k];
        float4 w = W4[k * JT + tj];
        acc.x = fmaf(x, w.x, acc.x);
        acc.y = fmaf(x, w.y, acc.y);
        acc.z = fmaf(x, w.z, acc.z);
        acc.w = fmaf(x, w.w, acc.w);
    }
    float dv = dinv[r];
    float4 hv = make_float4(acc.x * dv, acc.y * dv, acc.z * dv, acc.w * dv);
    size_t o = (size_t)r * Fout + (size_t)tj * 4;
    *reinterpret_cast<float4*>(hs  + o) = hv;
    *reinterpret_cast<float4*>(agg + o) = hv;   // self-loop init
}

// ---------------------------------------------------------------------------
// Edge scatter: agg[dst] += hs[src], vectorized float4 reductions (red.v4.f32)
// One thread per (edge, float4-chunk). Consecutive threads share an edge ->
// coalesced hs row reads; indices are broadcast through L1.
// ---------------------------------------------------------------------------
template <int Fout>
__global__ void scatter_kernel(const int* __restrict__ ei,
                               const float* __restrict__ hs,
                               float* __restrict__ agg, long long E) {
    constexpr int JT = Fout / 4;
    long long tid = (long long)blockIdx.x * blockDim.x + threadIdx.x;
    long long total = E * JT;
    if (tid >= total) return;
    long long e = tid / JT;
    int       c = (int)(tid - e * JT);
    long long s = ei[e];
    long long d = ei[E + e];
    float4 v = *reinterpret_cast<const float4*>(hs + s * Fout + (size_t)c * 4);
    float* p = agg + d * Fout + (size_t)c * 4;
    asm volatile("red.global.add.v4.f32 [%0], {%1,%2,%3,%4};"
                 :: "l"(p), "f"(v.x), "f"(v.y), "f"(v.z), "f"(v.w)
                 : "memory");
}

// ---------------------------------------------------------------------------
// MLP head: x4 = relu(dinv*agg4 + b4); t = relu(x4@Wf1+bf1); out = tanh(t@Wf2+bf2)
// One warp per node row.
// ---------------------------------------------------------------------------
__global__ void head_kernel(const float* __restrict__ agg,
                            const float* __restrict__ b4,
                            const float* __restrict__ Wf1,
                            const float* __restrict__ bf1,
                            const float* __restrict__ Wf2,
                            const float* __restrict__ bf2,
                            const float* __restrict__ dinv,
                            float* __restrict__ out, int N) {
    __shared__ float W1s[128 * 32];
    __shared__ float W2s[32 * 10];
    __shared__ float b4s[128], b1s[32], b2s[10];
    __shared__ float xs[8][128];
    __shared__ float ts[8][32];

    const int tid  = threadIdx.x;
    const int lane = tid & 31;
    const int w    = tid >> 5;

    for (int i = tid; i < 128 * 32; i += 256) W1s[i] = Wf1[i];
    for (int i = tid; i < 32 * 10;  i += 256) W2s[i] = Wf2[i];
    if (tid < 128) b4s[tid] = b4[tid];
    if (tid < 32)  b1s[tid] = bf1[tid];
    if (tid < 10)  b2s[tid] = bf2[tid];
    __syncthreads();

    const int r = blockIdx.x * 8 + w;
    if (r >= N) return;
    const float dv = dinv[r];

    for (int k = lane; k < 128; k += 32)
        xs[w][k] = fmaxf(fmaf(dv, agg[(size_t)r * 128 + k], b4s[k]), 0.f);
    __syncwarp();

    float t = b1s[lane];
#pragma unroll 8
    for (int k = 0; k < 128; k++)
        t = fmaf(xs[w][k], W1s[k * 32 + lane], t);
    ts[w][lane] = fmaxf(t, 0.f);
    __syncwarp();

    if (lane < 10) {
        float o = b2s[lane];
#pragma unroll
        for (int j = 0; j < 32; j++)
            o = fmaf(ts[w][j], W2s[j * 10 + lane], o);
        out[(size_t)r * 10 + lane] = tanhf(o);
    }
}

// ---------------------------------------------------------------------------
// Launch
// ---------------------------------------------------------------------------
static inline int cdiv(long long a, long long b) { return (int)((a + b - 1) / b); }

extern "C" void kernel_launch(void* const* d_in, const int* in_sizes, int n_in,
                              void* d_out, int out_size) {
    const float* x  = (const float*)d_in[0];
    const int*   ei = (const int*)d_in[1];       // int64 in reference, delivered as int32
    const float *W1 = (const float*)d_in[2],  *b1 = (const float*)d_in[3];
    const float *W2 = (const float*)d_in[4],  *b2 = (const float*)d_in[5];
    const float *W3 = (const float*)d_in[6],  *b3 = (const float*)d_in[7];
    const float *W4 = (const float*)d_in[8],  *b4 = (const float*)d_in[9];
    const float *Wf1 = (const float*)d_in[10], *bf1 = (const float*)d_in[11];
    const float *Wf2 = (const float*)d_in[12], *bf2 = (const float*)d_in[13];
    float* out = (float*)d_out;

    const int       N = in_sizes[0] / 128;
    const long long E = in_sizes[1] / 2;

    float *hs, *aggA, *aggB, *dinv;
    int* deg;
    cudaGetSymbolAddress((void**)&hs,   g_hs);
    cudaGetSymbolAddress((void**)&aggA, g_aggA);
    cudaGetSymbolAddress((void**)&aggB, g_aggB);
    cudaGetSymbolAddress((void**)&dinv, g_dinv);
    cudaGetSymbolAddress((void**)&deg,  g_deg);

    // degree + normalization
    zero_deg_kernel<<<cdiv(N, 256), 256>>>(deg, N);
    count_deg_kernel<<<cdiv(E, 256), 256>>>(ei, deg, E);
    dinv_kernel<<<cdiv(N, 256), 256>>>(deg, dinv, N);

    // Layer 1: 128 -> 16   (reads raw x, writes aggA)
    gemm_fused_kernel<128, 16, true><<<cdiv(N, 64), 256>>>(
        x, W1, nullptr, dinv, hs, aggA, N);
    scatter_kernel<16><<<cdiv(E * 4, 256), 256>>>(ei, hs, aggA, E);

    // Layer 2: 16 -> 32    (finalize L1 with b1, writes aggB)
    gemm_fused_kernel<16, 32, false><<<cdiv(N, 32), 256>>>(
        aggA, W2, b1, dinv, hs, aggB, N);
    scatter_kernel<32><<<cdiv(E * 8, 256), 256>>>(ei, hs, aggB, E);

    // Layer 3: 32 -> 64    (finalize L2 with b2, writes aggA)
    gemm_fused_kernel<32, 64, false><<<cdiv(N, 16), 256>>>(
        aggB, W3, b2, dinv, hs, aggA, N);
    scatter_kernel<64><<<cdiv(E * 16, 256), 256>>>(ei, hs, aggA, E);

    // Layer 4: 64 -> 128   (finalize L3 with b3, writes aggB)
    gemm_fused_kernel<64, 128, false><<<cdiv(N, 8), 256>>>(
        aggA, W4, b3, dinv, hs, aggB, N);
    scatter_kernel<128><<<cdiv(E * 32, 256), 256>>>(ei, hs, aggB, E);

    // Head: finalize L4 with b4, MLP 128->32->10, tanh
    head_kernel<<<cdiv(N, 8), 256>>>(aggB, b4, Wf1, bf1, Wf2, bf2, dinv, out, N);
}

// round 4
// speedup vs baseline: 1.8804x; 1.8804x over previous
#include <cuda_runtime.h>
#include <cuda_bf16.h>
#include <math.h>

#define N_NODES 100000
#define FMAX 128
#define E_MAX 1700000

// Scratch (static __device__ arrays — no allocation allowed)
__device__ float g_hs  [(size_t)N_NODES * FMAX];
__device__ float g_aggA[(size_t)N_NODES * FMAX];
__device__ float g_aggB[(size_t)N_NODES * FMAX];
__device__ float g_dinv[N_NODES];
__device__ int   g_deg [N_NODES];
__device__ int   g_cur [N_NODES];
__device__ int   g_rowptr[N_NODES + 1];
__device__ int   g_csr [E_MAX];

// ---------------------------------------------------------------------------
// Degree / normalization / CSR build
// ---------------------------------------------------------------------------
__global__ void zero_deg_kernel(int* __restrict__ deg, int n) {
    int i = blockIdx.x * blockDim.x + threadIdx.x;
    if (i < n) deg[i] = 0;
}

__global__ void count_deg_kernel(const int* __restrict__ ei,
                                 int* __restrict__ deg, long long E) {
    long long i = (long long)blockIdx.x * blockDim.x + threadIdx.x;
    if (i < E) atomicAdd(&deg[ei[E + i]], 1);
}

__global__ void dinv_kernel(const int* __restrict__ deg,
                            float* __restrict__ dinv,
                            int* __restrict__ cur, int n) {
    int i = blockIdx.x * blockDim.x + threadIdx.x;
    if (i < n) {
        dinv[i] = rsqrtf((float)deg[i] + 1.0f);
        cur[i] = 0;
    }
}

// Single-block exclusive scan over deg -> rowptr (N up to 1024*CH)
__global__ void scan_kernel(const int* __restrict__ deg,
                            int* __restrict__ rowptr, int N) {
    __shared__ int part[1024];
    const int tid = threadIdx.x;
    const int CH = (N + 1023) / 1024;
    const int base = tid * CH;
    int sum = 0;
    for (int i = 0; i < CH; i++) {
        int idx = base + i;
        if (idx < N) sum += deg[idx];
    }
    part[tid] = sum;
    __syncthreads();
    // Hillis-Steele inclusive scan
    for (int off = 1; off < 1024; off <<= 1) {
        int v = (tid >= off) ? part[tid - off] : 0;
        __syncthreads();
        part[tid] += v;
        __syncthreads();
    }
    int run = part[tid] - sum;  // exclusive offset for this chunk
    for (int i = 0; i < CH; i++) {
        int idx = base + i;
        if (idx < N) { rowptr[idx] = run; run += deg[idx]; }
    }
    if (tid == 1023) rowptr[N] = part[1023];
}

__global__ void fill_csr_kernel(const int* __restrict__ ei,
                                const int* __restrict__ rowptr,
                                int* __restrict__ cur,
                                int* __restrict__ csr, long long E) {
    long long e = (long long)blockIdx.x * blockDim.x + threadIdx.x;
    if (e >= E) return;
    int s = ei[e];
    int d = ei[E + e];
    int pos = atomicAdd(&cur[d], 1);
    csr[rowptr[d] + pos] = s;
}

// ---------------------------------------------------------------------------
// Fused GEMM: reads IN (raw x if FIRST, else prev agg with fused finalize
// relu(dinv*agg + b_prev)), computes hs = (X @ W) * dinv.
// Register-blocked 2 rows/thread, float4 x loads, padded smem (no conflicts).
// ---------------------------------------------------------------------------
template <int Fin, int Fout, int BLOCK, bool FIRST>
__global__ void gemm_fused_kernel(const float* __restrict__ in,
                                  const float* __restrict__ W,
                                  const float* __restrict__ b_prev,
                                  const float* __restrict__ dinv,
                                  float* __restrict__ hs,
                                  int N) {
    constexpr int JT     = Fout / 4;            // float4 chunks per row
    constexpr int GROUPS = BLOCK / JT;
    constexpr int ROWS   = GROUPS * 2;          // 2 rows per thread
    constexpr int XSTR   = Fin + 4;             // padded stride (floats)

    __shared__ __align__(16) float Ws[Fin * Fout];
    __shared__ __align__(16) float Xs[ROWS * XSTR];
    __shared__ float bs[Fin];

    const int tid = threadIdx.x;
    for (int i = tid; i < Fin * Fout; i += BLOCK) Ws[i] = W[i];
    if (!FIRST)
        for (int i = tid; i < Fin; i += BLOCK) bs[i] = b_prev[i];
    __syncthreads();

    const int row0 = blockIdx.x * ROWS;
    for (int i = tid; i < ROWS * Fin; i += BLOCK) {
        int rl = i / Fin, k = i % Fin;
        int r = row0 + rl;
        float v = 0.f;
        if (r < N) {
            v = in[(size_t)r * Fin + k];
            if (!FIRST) v = fmaxf(fmaf(dinv[r], v, bs[k]), 0.f);
        }
        Xs[rl * XSTR + k] = v;
    }
    __syncthreads();

    const int tj = tid % JT;
    const int tg = tid / JT;
    const int r0 = row0 + tg * 2;
    const int r1 = r0 + 1;

    float4 acc0 = make_float4(0.f, 0.f, 0.f, 0.f);
    float4 acc1 = make_float4(0.f, 0.f, 0.f, 0.f);
    const float4* W4 = reinterpret_cast<const float4*>(Ws);
    const float* x0 = &Xs[(tg * 2 + 0) * XSTR];
    const float* x1 = &Xs[(tg * 2 + 1) * XSTR];

#pragma unroll
    for (int k0 = 0; k0 < Fin; k0 += 4) {
        float4 w0 = W4[(k0 + 0) * JT + tj];
        float4 w1 = W4[(k0 + 1) * JT + tj];
        float4 w2 = W4[(k0 + 2) * JT + tj];
        float4 w3 = W4[(k0 + 3) * JT + tj];
        float4 xa = *reinterpret_cast<const float4*>(x0 + k0);
        float4 xb = *reinterpret_cast<const float4*>(x1 + k0);
        acc0.x = fmaf(xa.x, w0.x, acc0.x); acc0.y = fmaf(xa.x, w0.y, acc0.y);
        acc0.z = fmaf(xa.x, w0.z, acc0.z); acc0.w = fmaf(xa.x, w0.w, acc0.w);
        acc0.x = fmaf(xa.y, w1.x, acc0.x); acc0.y = fmaf(xa.y, w1.y, acc0.y);
        acc0.z = fmaf(xa.y, w1.z, acc0.z); acc0.w = fmaf(xa.y, w1.w, acc0.w);
        acc0.x = fmaf(xa.z, w2.x, acc0.x); acc0.y = fmaf(xa.z, w2.y, acc0.y);
        acc0.z = fmaf(xa.z, w2.z, acc0.z); acc0.w = fmaf(xa.z, w2.w, acc0.w);
        acc0.x = fmaf(xa.w, w3.x, acc0.x); acc0.y = fmaf(xa.w, w3.y, acc0.y);
        acc0.z = fmaf(xa.w, w3.z, acc0.z); acc0.w = fmaf(xa.w, w3.w, acc0.w);
        acc1.x = fmaf(xb.x, w0.x, acc1.x); acc1.y = fmaf(xb.x, w0.y, acc1.y);
        acc1.z = fmaf(xb.x, w0.z, acc1.z); acc1.w = fmaf(xb.x, w0.w, acc1.w);
        acc1.x = fmaf(xb.y, w1.x, acc1.x); acc1.y = fmaf(xb.y, w1.y, acc1.y);
        acc1.z = fmaf(xb.y, w1.z, acc1.z); acc1.w = fmaf(xb.y, w1.w, acc1.w);
        acc1.x = fmaf(xb.z, w2.x, acc1.x); acc1.y = fmaf(xb.z, w2.y, acc1.y);
        acc1.z = fmaf(xb.z, w2.z, acc1.z); acc1.w = fmaf(xb.z, w2.w, acc1.w);
        acc1.x = fmaf(xb.w, w3.x, acc1.x); acc1.y = fmaf(xb.w, w3.y, acc1.y);
        acc1.z = fmaf(xb.w, w3.z, acc1.z); acc1.w = fmaf(xb.w, w3.w, acc1.w);
    }

    if (r0 < N) {
        float dv = dinv[r0];
        float4 hv = make_float4(acc0.x * dv, acc0.y * dv, acc0.z * dv, acc0.w * dv);
        *reinterpret_cast<float4*>(hs + (size_t)r0 * Fout + (size_t)tj * 4) = hv;
    }
    if (r1 < N) {
        float dv = dinv[r1];
        float4 hv = make_float4(acc1.x * dv, acc1.y * dv, acc1.z * dv, acc1.w * dv);
        *reinterpret_cast<float4*>(hs + (size_t)r1 * Fout + (size_t)tj * 4) = hv;
    }
}

// ---------------------------------------------------------------------------
// CSR gather aggregation: agg[r] = hs[r] + sum_{j in row r} hs[csr[j]]
// LPR = F/4 lanes cooperate on one dst row; no atomics, coalesced row reads.
// ---------------------------------------------------------------------------
template <int F>
__global__ void gather_kernel(const int* __restrict__ rowptr,
                              const int* __restrict__ csr,
                              const float* __restrict__ hs,
                              float* __restrict__ agg, int N) {
    constexpr int LPR = F / 4;        // lanes per row
    constexpr int RPB = 256 / LPR;    // rows per block
    const int tid = threadIdx.x;
    const int c    = tid % LPR;
    const int rloc = tid / LPR;
    const int r = blockIdx.x * RPB + rloc;
    if (r >= N) return;

    const float4* hs4 = reinterpret_cast<const float4*>(hs);
    float4 acc = hs4[(size_t)r * LPR + c];  // self-loop term

    const int beg = rowptr[r];
    const int end = rowptr[r + 1];
    int j = beg;
    for (; j + 4 <= end; j += 4) {
        int s0 = csr[j], s1 = csr[j + 1], s2 = csr[j + 2], s3 = csr[j + 3];
        float4 v0 = hs4[(size_t)s0 * LPR + c];
        float4 v1 = hs4[(size_t)s1 * LPR + c];
        float4 v2 = hs4[(size_t)s2 * LPR + c];
        float4 v3 = hs4[(size_t)s3 * LPR + c];
        acc.x += v0.x + v1.x + v2.x + v3.x;
        acc.y += v0.y + v1.y + v2.y + v3.y;
        acc.z += v0.z + v1.z + v2.z + v3.z;
        acc.w += v0.w + v1.w + v2.w + v3.w;
    }
    for (; j < end; j++) {
        int s = csr[j];
        float4 v = hs4[(size_t)s * LPR + c];
        acc.x += v.x; acc.y += v.y; acc.z += v.z; acc.w += v.w;
    }
    reinterpret_cast<float4*>(agg)[(size_t)r * LPR + c] = acc;
}

// ---------------------------------------------------------------------------
// MLP head: x4 = relu(dinv*agg4 + b4); t = relu(x4@Wf1+bf1); out = tanh(t@Wf2+bf2)
// ---------------------------------------------------------------------------
__global__ void head_kernel(const float* __restrict__ agg,
                            const float* __restrict__ b4,
                            const float* __restrict__ Wf1,
                            const float* __restrict__ bf1,
                            const float* __restrict__ Wf2,
                            const float* __restrict__ bf2,
                            const float* __restrict__ dinv,
                            float* __restrict__ out, int N) {
    __shared__ float W1s[128 * 32];
    __shared__ float W2s[32 * 10];
    __shared__ float b4s[128], b1s[32], b2s[10];
    __shared__ float xs[8][128];
    __shared__ float ts[8][32];

    const int tid  = threadIdx.x;
    const int lane = tid & 31;
    const int w    = tid >> 5;

    for (int i = tid; i < 128 * 32; i += 256) W1s[i] = Wf1[i];
    for (int i = tid; i < 32 * 10;  i += 256) W2s[i] = Wf2[i];
    if (tid < 128) b4s[tid] = b4[tid];
    if (tid < 32)  b1s[tid] = bf1[tid];
    if (tid < 10)  b2s[tid] = bf2[tid];
    __syncthreads();

    const int r = blockIdx.x * 8 + w;
    if (r >= N) return;
    const float dv = dinv[r];

    for (int k = lane; k < 128; k += 32)
        xs[w][k] = fmaxf(fmaf(dv, agg[(size_t)r * 128 + k], b4s[k]), 0.f);
    __syncwarp();

    float t = b1s[lane];
#pragma unroll 8
    for (int k = 0; k < 128; k++)
        t = fmaf(xs[w][k], W1s[k * 32 + lane], t);
    ts[w][lane] = fmaxf(t, 0.f);
    __syncwarp();

    if (lane < 10) {
        float o = b2s[lane];
#pragma unroll
        for (int j = 0; j < 32; j++)
            o = fmaf(ts[w][j], W2s[j * 10 + lane], o);
        out[(size_t)r * 10 + lane] = tanhf(o);
    }
}

// ---------------------------------------------------------------------------
// Launch
// ---------------------------------------------------------------------------
static inline int cdiv(long long a, long long b) { return (int)((a + b - 1) / b); }

extern "C" void kernel_launch(void* const* d_in, const int* in_sizes, int n_in,
                              void* d_out, int out_size) {
    const float* x  = (const float*)d_in[0];
    const int*   ei = (const int*)d_in[1];       // int64 in reference, delivered as int32
    const float *W1 = (const float*)d_in[2],  *b1 = (const float*)d_in[3];
    const float *W2 = (const float*)d_in[4],  *b2 = (const float*)d_in[5];
    const float *W3 = (const float*)d_in[6],  *b3 = (const float*)d_in[7];
    const float *W4 = (const float*)d_in[8],  *b4 = (const float*)d_in[9];
    const float *Wf1 = (const float*)d_in[10], *bf1 = (const float*)d_in[11];
    const float *Wf2 = (const float*)d_in[12], *bf2 = (const float*)d_in[13];
    float* out = (float*)d_out;

    const int       N = in_sizes[0] / 128;
    const long long E = in_sizes[1] / 2;

    float *hs, *aggA, *aggB, *dinv;
    int *deg, *cur, *rowptr, *csr;
    cudaGetSymbolAddress((void**)&hs,     g_hs);
    cudaGetSymbolAddress((void**)&aggA,   g_aggA);
    cudaGetSymbolAddress((void**)&aggB,   g_aggB);
    cudaGetSymbolAddress((void**)&dinv,   g_dinv);
    cudaGetSymbolAddress((void**)&deg,    g_deg);
    cudaGetSymbolAddress((void**)&cur,    g_cur);
    cudaGetSymbolAddress((void**)&rowptr, g_rowptr);
    cudaGetSymbolAddress((void**)&csr,    g_csr);

    // degree + normalization + CSR build (graph is static across layers)
    zero_deg_kernel<<<cdiv(N, 256), 256>>>(deg, N);
    count_deg_kernel<<<cdiv(E, 256), 256>>>(ei, deg, E);
    dinv_kernel<<<cdiv(N, 256), 256>>>(deg, dinv, cur, N);
    scan_kernel<<<1, 1024>>>(deg, rowptr, N);
    fill_csr_kernel<<<cdiv(E, 256), 256>>>(ei, rowptr, cur, csr, E);

    // Layer 1: 128 -> 16
    gemm_fused_kernel<128, 16, 128, true><<<cdiv(N, 64), 128>>>(
        x, W1, nullptr, dinv, hs, N);
    gather_kernel<16><<<cdiv(N, 64), 256>>>(rowptr, csr, hs, aggA, N);

    // Layer 2: 16 -> 32
    gemm_fused_kernel<16, 32, 256, false><<<cdiv(N, 64), 256>>>(
        aggA, W2, b1, dinv, hs, N);
    gather_kernel<32><<<cdiv(N, 32), 256>>>(rowptr, csr, hs, aggB, N);

    // Layer 3: 32 -> 64
    gemm_fused_kernel<32, 64, 256, false><<<cdiv(N, 32), 256>>>(
        aggB, W3, b2, dinv, hs, N);
    gather_kernel<64><<<cdiv(N, 16), 256>>>(rowptr, csr, hs, aggA, N);

    // Layer 4: 64 -> 128
    gemm_fused_kernel<64, 128, 256, false><<<cdiv(N, 16), 256>>>(
        aggA, W4, b3, dinv, hs, N);
    gather_kernel<128><<<cdiv(N, 8), 256>>>(rowptr, csr, hs, aggB, N);

    // Head: finalize L4 with b4, MLP 128->32->10, tanh
    head_kernel<<<cdiv(N, 8), 256>>>(aggB, b4, Wf1, bf1, Wf2, bf2, dinv, out, N);
}

// round 6
// speedup vs baseline: 2.2523x; 1.1977x over previous
#include <cuda_runtime.h>
#include <cuda_bf16.h>
#include <math.h>

#define N_NODES 100000
#define FMAX 128
#define E_MAX 1700000
#define SCAN_B 256
#define SCAN_NB ((N_NODES + SCAN_B - 1) / SCAN_B)   // 391

// Scratch (static __device__ arrays — no allocation allowed)
__device__ float g_hs  [(size_t)N_NODES * FMAX];
__device__ float g_aggA[(size_t)N_NODES * FMAX];
__device__ float g_aggB[(size_t)N_NODES * FMAX];
__device__ float g_dinv[N_NODES];
__device__ int   g_deg [N_NODES];
__device__ int   g_cur [N_NODES];
__device__ int   g_rowptr[N_NODES + 1];
__device__ int   g_csr [E_MAX];
__device__ int   g_bsum[SCAN_NB];

// ---------------------------------------------------------------------------
// Degree / normalization
// ---------------------------------------------------------------------------
__global__ void zero_deg_kernel(int* __restrict__ deg, int n) {
    int i = blockIdx.x * blockDim.x + threadIdx.x;
    if (i < n) deg[i] = 0;
}

__global__ void count_deg_kernel(const int* __restrict__ ei,
                                 int* __restrict__ deg, long long E) {
    long long i = (long long)blockIdx.x * blockDim.x + threadIdx.x;
    if (i < E) atomicAdd(&deg[ei[E + i]], 1);
}

__global__ void dinv_kernel(const int* __restrict__ deg,
                            float* __restrict__ dinv,
                            int* __restrict__ cur, int n) {
    int i = blockIdx.x * blockDim.x + threadIdx.x;
    if (i < n) {
        dinv[i] = rsqrtf((float)deg[i] + 1.0f);
        cur[i] = 0;
    }
}

// ---------------------------------------------------------------------------
// Multi-block exclusive scan: deg -> rowptr
// Phase 1: per-block sums (coalesced).  Phase 2: scan the 391 partials in one
// block.  Phase 3: block-local scan + add offset, write rowptr.
// ---------------------------------------------------------------------------
__global__ void scan_phase1_kernel(const int* __restrict__ deg,
                                   int* __restrict__ bsum, int N) {
    __shared__ int red[SCAN_B];
    const int tid = threadIdx.x;
    const int i = blockIdx.x * SCAN_B + tid;
    int v = (i < N) ? deg[i] : 0;
    red[tid] = v;
    __syncthreads();
    for (int off = SCAN_B / 2; off > 0; off >>= 1) {
        if (tid < off) red[tid] += red[tid + off];
        __syncthreads();
    }
    if (tid == 0) bsum[blockIdx.x] = red[0];
}

__global__ void scan_phase2_kernel(int* __restrict__ bsum, int NB) {
    __shared__ int s[512];
    const int tid = threadIdx.x;
    int v = (tid < NB) ? bsum[tid] : 0;
    s[tid] = v;
    __syncthreads();
    for (int off = 1; off < 512; off <<= 1) {
        int t = (tid >= off) ? s[tid - off] : 0;
        __syncthreads();
        s[tid] += t;
        __syncthreads();
    }
    if (tid < NB) bsum[tid] = s[tid] - v;   // exclusive
}

__global__ void scan_phase3_kernel(const int* __restrict__ deg,
                                   const int* __restrict__ bsum,
                                   int* __restrict__ rowptr, int N) {
    __shared__ int s[SCAN_B];
    const int tid = threadIdx.x;
    const int i = blockIdx.x * SCAN_B + tid;
    int v = (i < N) ? deg[i] : 0;
    s[tid] = v;
    __syncthreads();
    for (int off = 1; off < SCAN_B; off <<= 1) {
        int t = (tid >= off) ? s[tid - off] : 0;
        __syncthreads();
        s[tid] += t;
        __syncthreads();
    }
    int excl = bsum[blockIdx.x] + s[tid] - v;
    if (i < N) {
        rowptr[i] = excl;
        if (i == N - 1) rowptr[N] = excl + v;
    }
}

__global__ void fill_csr_kernel(const int* __restrict__ ei,
                                const int* __restrict__ rowptr,
                                int* __restrict__ cur,
                                int* __restrict__ csr, long long E) {
    long long e = (long long)blockIdx.x * blockDim.x + threadIdx.x;
    if (e >= E) return;
    int s = ei[e];
    int d = ei[E + e];
    int pos = atomicAdd(&cur[d], 1);
    csr[rowptr[d] + pos] = s;
}

// ---------------------------------------------------------------------------
// Fused GEMM: reads IN (raw x if FIRST, else prev agg with fused finalize
// relu(dinv*agg + b_prev)), computes hs = (X @ W) * dinv.
// Register-blocked 2 rows/thread, float4 x loads, padded smem (no conflicts).
// ---------------------------------------------------------------------------
template <int Fin, int Fout, int BLOCK, bool FIRST>
__global__ void gemm_fused_kernel(const float* __restrict__ in,
                                  const float* __restrict__ W,
                                  const float* __restrict__ b_prev,
                                  const float* __restrict__ dinv,
                                  float* __restrict__ hs,
                                  int N) {
    constexpr int JT     = Fout / 4;            // float4 chunks per row
    constexpr int GROUPS = BLOCK / JT;
    constexpr int ROWS   = GROUPS * 2;          // 2 rows per thread
    constexpr int XSTR   = Fin + 4;             // padded stride (floats)

    __shared__ __align__(16) float Ws[Fin * Fout];
    __shared__ __align__(16) float Xs[ROWS * XSTR];
    __shared__ float bs[Fin];

    const int tid = threadIdx.x;
    for (int i = tid; i < Fin * Fout; i += BLOCK) Ws[i] = W[i];
    if (!FIRST)
        for (int i = tid; i < Fin; i += BLOCK) bs[i] = b_prev[i];
    __syncthreads();

    const int row0 = blockIdx.x * ROWS;
    for (int i = tid; i < ROWS * Fin; i += BLOCK) {
        int rl = i / Fin, k = i % Fin;
        int r = row0 + rl;
        float v = 0.f;
        if (r < N) {
            v = in[(size_t)r * Fin + k];
            if (!FIRST) v = fmaxf(fmaf(dinv[r], v, bs[k]), 0.f);
        }
        Xs[rl * XSTR + k] = v;
    }
    __syncthreads();

    const int tj = tid % JT;
    const int tg = tid / JT;
    const int r0 = row0 + tg * 2;
    const int r1 = r0 + 1;

    float4 acc0 = make_float4(0.f, 0.f, 0.f, 0.f);
    float4 acc1 = make_float4(0.f, 0.f, 0.f, 0.f);
    const float4* W4 = reinterpret_cast<const float4*>(Ws);
    const float* x0 = &Xs[(tg * 2 + 0) * XSTR];
    const float* x1 = &Xs[(tg * 2 + 1) * XSTR];

#pragma unroll
    for (int k0 = 0; k0 < Fin; k0 += 4) {
        float4 w0 = W4[(k0 + 0) * JT + tj];
        float4 w1 = W4[(k0 + 1) * JT + tj];
        float4 w2 = W4[(k0 + 2) * JT + tj];
        float4 w3 = W4[(k0 + 3) * JT + tj];
        float4 xa = *reinterpret_cast<const float4*>(x0 + k0);
        float4 xb = *reinterpret_cast<const float4*>(x1 + k0);
        acc0.x = fmaf(xa.x, w0.x, acc0.x); acc0.y = fmaf(xa.x, w0.y, acc0.y);
        acc0.z = fmaf(xa.x, w0.z, acc0.z); acc0.w = fmaf(xa.x, w0.w, acc0.w);
        acc0.x = fmaf(xa.y, w1.x, acc0.x); acc0.y = fmaf(xa.y, w1.y, acc0.y);
        acc0.z = fmaf(xa.y, w1.z, acc0.z); acc0.w = fmaf(xa.y, w1.w, acc0.w);
        acc0.x = fmaf(xa.z, w2.x, acc0.x); acc0.y = fmaf(xa.z, w2.y, acc0.y);
        acc0.z = fmaf(xa.z, w2.z, acc0.z); acc0.w = fmaf(xa.z, w2.w, acc0.w);
        acc0.x = fmaf(xa.w, w3.x, acc0.x); acc0.y = fmaf(xa.w, w3.y, acc0.y);
        acc0.z = fmaf(xa.w, w3.z, acc0.z); acc0.w = fmaf(xa.w, w3.w, acc0.w);
        acc1.x = fmaf(xb.x, w0.x, acc1.x); acc1.y = fmaf(xb.x, w0.y, acc1.y);
        acc1.z = fmaf(xb.x, w0.z, acc1.z); acc1.w = fmaf(xb.x, w0.w, acc1.w);
        acc1.x = fmaf(xb.y, w1.x, acc1.x); acc1.y = fmaf(xb.y, w1.y, acc1.y);
        acc1.z = fmaf(xb.y, w1.z, acc1.z); acc1.w = fmaf(xb.y, w1.w, acc1.w);
        acc1.x = fmaf(xb.z, w2.x, acc1.x); acc1.y = fmaf(xb.z, w2.y, acc1.y);
        acc1.z = fmaf(xb.z, w2.z, acc1.z); acc1.w = fmaf(xb.z, w2.w, acc1.w);
        acc1.x = fmaf(xb.w, w3.x, acc1.x); acc1.y = fmaf(xb.w, w3.y, acc1.y);
        acc1.z = fmaf(xb.w, w3.z, acc1.z); acc1.w = fmaf(xb.w, w3.w, acc1.w);
    }

    if (r0 < N) {
        float dv = dinv[r0];
        float4 hv = make_float4(acc0.x * dv, acc0.y * dv, acc0.z * dv, acc0.w * dv);
        *reinterpret_cast<float4*>(hs + (size_t)r0 * Fout + (size_t)tj * 4) = hv;
    }
    if (r1 < N) {
        float dv = dinv[r1];
        float4 hv = make_float4(acc1.x * dv, acc1.y * dv, acc1.z * dv, acc1.w * dv);
        *reinterpret_cast<float4*>(hs + (size_t)r1 * Fout + (size_t)tj * 4) = hv;
    }
}

// ---------------------------------------------------------------------------
// CSR gather aggregation: agg[r] = hs[r] + sum_{j in row r} hs[csr[j]]
// ---------------------------------------------------------------------------
template <int F>
__global__ void gather_kernel(const int* __restrict__ rowptr,
                              const int* __restrict__ csr,
                              const float* __restrict__ hs,
                              float* __restrict__ agg, int N) {
    constexpr int LPR = F / 4;        // lanes per row
    constexpr int RPB = 256 / LPR;    // rows per block
    const int tid = threadIdx.x;
    const int c    = tid % LPR;
    const int rloc = tid / LPR;
    const int r = blockIdx.x * RPB + rloc;
    if (r >= N) return;

    const float4* hs4 = reinterpret_cast<const float4*>(hs);
    float4 acc = hs4[(size_t)r * LPR + c];  // self-loop term

    const int beg = rowptr[r];
    const int end = rowptr[r + 1];
    int j = beg;
    for (; j + 4 <= end; j += 4) {
        int s0 = csr[j], s1 = csr[j + 1], s2 = csr[j + 2], s3 = csr[j + 3];
        float4 v0 = hs4[(size_t)s0 * LPR + c];
        float4 v1 = hs4[(size_t)s1 * LPR + c];
        float4 v2 = hs4[(size_t)s2 * LPR + c];
        float4 v3 = hs4[(size_t)s3 * LPR + c];
        acc.x += v0.x + v1.x + v2.x + v3.x;
        acc.y += v0.y + v1.y + v2.y + v3.y;
        acc.z += v0.z + v1.z + v2.z + v3.z;
        acc.w += v0.w + v1.w + v2.w + v3.w;
    }
    for (; j < end; j++) {
        int s = csr[j];
        float4 v = hs4[(size_t)s * LPR + c];
        acc.x += v.x; acc.y += v.y; acc.z += v.z; acc.w += v.w;
    }
    reinterpret_cast<float4*>(agg)[(size_t)r * LPR + c] = acc;
}

// ---------------------------------------------------------------------------
// MLP head: x4 = relu(dinv*agg4 + b4); t = relu(x4@Wf1+bf1); out = tanh(t@Wf2+bf2)
// ---------------------------------------------------------------------------
__global__ void head_kernel(const float* __restrict__ agg,
                            const float* __restrict__ b4,
                            const float* __restrict__ Wf1,
                            const float* __restrict__ bf1,
                            const float* __restrict__ Wf2,
                            const float* __restrict__ bf2,
                            const float* __restrict__ dinv,
                            float* __restrict__ out, int N) {
    __shared__ float W1s[128 * 32];
    __shared__ float W2s[32 * 10];
    __shared__ float b4s[128], b1s[32], b2s[10];
    __shared__ float xs[8][128];
    __shared__ float ts[8][32];

    const int tid  = threadIdx.x;
    const int lane = tid & 31;
    const int w    = tid >> 5;

    for (int i = tid; i < 128 * 32; i += 256) W1s[i] = Wf1[i];
    for (int i = tid; i < 32 * 10;  i += 256) W2s[i] = Wf2[i];
    if (tid < 128) b4s[tid] = b4[tid];
    if (tid < 32)  b1s[tid] = bf1[tid];
    if (tid < 10)  b2s[tid] = bf2[tid];
    __syncthreads();

    const int r = blockIdx.x * 8 + w;
    if (r >= N) return;
    const float dv = dinv[r];

    for (int k = lane; k < 128; k += 32)
        xs[w][k] = fmaxf(fmaf(dv, agg[(size_t)r * 128 + k], b4s[k]), 0.f);
    __syncwarp();

    float t = b1s[lane];
#pragma unroll 8
    for (int k = 0; k < 128; k++)
        t = fmaf(xs[w][k], W1s[k * 32 + lane], t);
    ts[w][lane] = fmaxf(t, 0.f);
    __syncwarp();

    if (lane < 10) {
        float o = b2s[lane];
#pragma unroll
        for (int j = 0; j < 32; j++)
            o = fmaf(ts[w][j], W2s[j * 10 + lane], o);
        out[(size_t)r * 10 + lane] = tanhf(o);
    }
}

// ---------------------------------------------------------------------------
// Launch
// ---------------------------------------------------------------------------
static inline int cdiv(long long a, long long b) { return (int)((a + b - 1) / b); }

extern "C" void kernel_launch(void* const* d_in, const int* in_sizes, int n_in,
                              void* d_out, int out_size) {
    const float* x  = (const float*)d_in[0];
    const int*   ei = (const int*)d_in[1];       // int64 in reference, delivered as int32
    const float *W1 = (const float*)d_in[2],  *b1 = (const float*)d_in[3];
    const float *W2 = (const float*)d_in[4],  *b2 = (const float*)d_in[5];
    const float *W3 = (const float*)d_in[6],  *b3 = (const float*)d_in[7];
    const float *W4 = (const float*)d_in[8],  *b4 = (const float*)d_in[9];
    const float *Wf1 = (const float*)d_in[10], *bf1 = (const float*)d_in[11];
    const float *Wf2 = (const float*)d_in[12], *bf2 = (const float*)d_in[13];
    float* out = (float*)d_out;

    const int       N = in_sizes[0] / 128;
    const long long E = in_sizes[1] / 2;

    float *hs, *aggA, *aggB, *dinv;
    int *deg, *cur, *rowptr, *csr, *bsum;
    cudaGetSymbolAddress((void**)&hs,     g_hs);
    cudaGetSymbolAddress((void**)&aggA,   g_aggA);
    cudaGetSymbolAddress((void**)&aggB,   g_aggB);
    cudaGetSymbolAddress((void**)&dinv,   g_dinv);
    cudaGetSymbolAddress((void**)&deg,    g_deg);
    cudaGetSymbolAddress((void**)&cur,    g_cur);
    cudaGetSymbolAddress((void**)&rowptr, g_rowptr);
    cudaGetSymbolAddress((void**)&csr,    g_csr);
    cudaGetSymbolAddress((void**)&bsum,   g_bsum);

    const int NB = (N + SCAN_B - 1) / SCAN_B;

    // degree + normalization + CSR build (graph is static across layers)
    zero_deg_kernel<<<cdiv(N, 256), 256>>>(deg, N);
    count_deg_kernel<<<cdiv(E, 256), 256>>>(ei, deg, E);
    dinv_kernel<<<cdiv(N, 256), 256>>>(deg, dinv, cur, N);
    scan_phase1_kernel<<<NB, SCAN_B>>>(deg, bsum, N);
    scan_phase2_kernel<<<1, 512>>>(bsum, NB);
    scan_phase3_kernel<<<NB, SCAN_B>>>(deg, bsum, rowptr, N);
    fill_csr_kernel<<<cdiv(E, 256), 256>>>(ei, rowptr, cur, csr, E);

    // Layer 1: 128 -> 16
    gemm_fused_kernel<128, 16, 128, true><<<cdiv(N, 64), 128>>>(
        x, W1, nullptr, dinv, hs, N);
    gather_kernel<16><<<cdiv(N, 64), 256>>>(rowptr, csr, hs, aggA, N);

    // Layer 2: 16 -> 32
    gemm_fused_kernel<16, 32, 256, false><<<cdiv(N, 64), 256>>>(
        aggA, W2, b1, dinv, hs, N);
    gather_kernel<32><<<cdiv(N, 32), 256>>>(rowptr, csr, hs, aggB, N);

    // Layer 3: 32 -> 64
    gemm_fused_kernel<32, 64, 256, false><<<cdiv(N, 32), 256>>>(
        aggB, W3, b2, dinv, hs, N);
    gather_kernel<64><<<cdiv(N, 16), 256>>>(rowptr, csr, hs, aggA, N);

    // Layer 4: 64 -> 128
    gemm_fused_kernel<64, 128, 256, false><<<cdiv(N, 16), 256>>>(
        aggA, W4, b3, dinv, hs, N);
    gather_kernel<128><<<cdiv(N, 8), 256>>>(rowptr, csr, hs, aggB, N);

    // Head: finalize L4 with b4, MLP 128->32->10, tanh
    head_kernel<<<cdiv(N, 8), 256>>>(aggB, b4, Wf1, bf1, Wf2, bf2, dinv, out, N);
}

// round 8
// speedup vs baseline: 2.6393x; 1.1718x over previous
#include <cuda_runtime.h>
#include <cuda_bf16.h>
#include <math.h>

#define N_NODES 100000
#define FMAX 128
#define E_MAX 1700000
#define SCAN_B 256
#define SCAN_NB ((N_NODES + SCAN_B - 1) / SCAN_B)   // 391

// Scratch (static __device__ arrays — no allocation allowed)
__device__ float g_hs  [(size_t)N_NODES * FMAX];
__device__ float g_aggA[(size_t)N_NODES * FMAX];
__device__ float g_aggB[(size_t)N_NODES * FMAX];
__device__ float g_dinv[N_NODES];
__device__ int   g_deg [N_NODES];
__device__ int   g_cur [N_NODES];
__device__ int   g_rowptr[N_NODES + 1];
__device__ int   g_csr [E_MAX];
__device__ int   g_bsum[SCAN_NB];

// ---------------------------------------------------------------------------
// Degree / normalization
// ---------------------------------------------------------------------------
__global__ void zero_deg_kernel(int* __restrict__ deg, int n) {
    int i = blockIdx.x * blockDim.x + threadIdx.x;
    if (i < n) deg[i] = 0;
}

__global__ void count_deg_kernel(const int* __restrict__ ei,
                                 int* __restrict__ deg, long long E) {
    long long i = (long long)blockIdx.x * blockDim.x + threadIdx.x;
    if (i < E) atomicAdd(&deg[ei[E + i]], 1);
}

__global__ void dinv_kernel(const int* __restrict__ deg,
                            float* __restrict__ dinv,
                            int* __restrict__ cur, int n) {
    int i = blockIdx.x * blockDim.x + threadIdx.x;
    if (i < n) {
        dinv[i] = rsqrtf((float)deg[i] + 1.0f);
        cur[i] = 0;
    }
}

// ---------------------------------------------------------------------------
// Multi-block exclusive scan: deg -> rowptr
// ---------------------------------------------------------------------------
__global__ void scan_phase1_kernel(const int* __restrict__ deg,
                                   int* __restrict__ bsum, int N) {
    __shared__ int red[SCAN_B];
    const int tid = threadIdx.x;
    const int i = blockIdx.x * SCAN_B + tid;
    int v = (i < N) ? deg[i] : 0;
    red[tid] = v;
    __syncthreads();
    for (int off = SCAN_B / 2; off > 0; off >>= 1) {
        if (tid < off) red[tid] += red[tid + off];
        __syncthreads();
    }
    if (tid == 0) bsum[blockIdx.x] = red[0];
}

__global__ void scan_phase2_kernel(int* __restrict__ bsum, int NB) {
    __shared__ int s[512];
    const int tid = threadIdx.x;
    int v = (tid < NB) ? bsum[tid] : 0;
    s[tid] = v;
    __syncthreads();
    for (int off = 1; off < 512; off <<= 1) {
        int t = (tid >= off) ? s[tid - off] : 0;
        __syncthreads();
        s[tid] += t;
        __syncthreads();
    }
    if (tid < NB) bsum[tid] = s[tid] - v;   // exclusive
}

__global__ void scan_phase3_kernel(const int* __restrict__ deg,
                                   const int* __restrict__ bsum,
                                   int* __restrict__ rowptr, int N) {
    __shared__ int s[SCAN_B];
    const int tid = threadIdx.x;
    const int i = blockIdx.x * SCAN_B + tid;
    int v = (i < N) ? deg[i] : 0;
    s[tid] = v;
    __syncthreads();
    for (int off = 1; off < SCAN_B; off <<= 1) {
        int t = (tid >= off) ? s[tid - off] : 0;
        __syncthreads();
        s[tid] += t;
        __syncthreads();
    }
    int excl = bsum[blockIdx.x] + s[tid] - v;
    if (i < N) {
        rowptr[i] = excl;
        if (i == N - 1) rowptr[N] = excl + v;
    }
}

__global__ void fill_csr_kernel(const int* __restrict__ ei,
                                const int* __restrict__ rowptr,
                                int* __restrict__ cur,
                                int* __restrict__ csr, long long E) {
    long long e = (long long)blockIdx.x * blockDim.x + threadIdx.x;
    if (e >= E) return;
    int s = ei[e];
    int d = ei[E + e];
    int pos = atomicAdd(&cur[d], 1);
    csr[rowptr[d] + pos] = s;
}

// ---------------------------------------------------------------------------
// GEMM: out = f(IN) @ W with configurable transforms.
//  IN_SCALE: input row scaled by dinv[r] (propagate-first layers)
//  OUT_BIAS_RELU: out = relu(acc + b[j])
//  OUT_SCALE: out *= dinv[r]  (emit u = dinv*x for the next gather)
// ---------------------------------------------------------------------------
template <int Fin, int Fout, int BLOCK, bool IN_SCALE, bool OUT_BIAS_RELU, bool OUT_SCALE>
__global__ void gemm_kernel(const float* __restrict__ in,
                            const float* __restrict__ W,
                            const float* __restrict__ b_out,
                            const float* __restrict__ dinv,
                            float* __restrict__ out,
                            int N) {
    constexpr int JT     = Fout / 4;            // float4 chunks per row
    constexpr int GROUPS = BLOCK / JT;
    constexpr int ROWS   = GROUPS * 2;          // 2 rows per thread
    constexpr int XSTR   = Fin + 4;             // padded stride (floats)

    __shared__ __align__(16) float Ws[Fin * Fout];
    __shared__ __align__(16) float Xs[ROWS * XSTR];

    const int tid = threadIdx.x;
    for (int i = tid; i < Fin * Fout; i += BLOCK) Ws[i] = W[i];
    __syncthreads();

    const int row0 = blockIdx.x * ROWS;
    for (int i = tid; i < ROWS * Fin; i += BLOCK) {
        int rl = i / Fin, k = i % Fin;
        int r = row0 + rl;
        float v = 0.f;
        if (r < N) {
            v = in[(size_t)r * Fin + k];
            if (IN_SCALE) v *= dinv[r];
        }
        Xs[rl * XSTR + k] = v;
    }
    __syncthreads();

    const int tj = tid % JT;
    const int tg = tid / JT;
    const int r0 = row0 + tg * 2;
    const int r1 = r0 + 1;

    float4 acc0 = make_float4(0.f, 0.f, 0.f, 0.f);
    float4 acc1 = make_float4(0.f, 0.f, 0.f, 0.f);
    const float4* W4 = reinterpret_cast<const float4*>(Ws);
    const float* x0 = &Xs[(tg * 2 + 0) * XSTR];
    const float* x1 = &Xs[(tg * 2 + 1) * XSTR];

#pragma unroll
    for (int k0 = 0; k0 < Fin; k0 += 4) {
        float4 w0 = W4[(k0 + 0) * JT + tj];
        float4 w1 = W4[(k0 + 1) * JT + tj];
        float4 w2 = W4[(k0 + 2) * JT + tj];
        float4 w3 = W4[(k0 + 3) * JT + tj];
        float4 xa = *reinterpret_cast<const float4*>(x0 + k0);
        float4 xb = *reinterpret_cast<const float4*>(x1 + k0);
        acc0.x = fmaf(xa.x, w0.x, acc0.x); acc0.y = fmaf(xa.x, w0.y, acc0.y);
        acc0.z = fmaf(xa.x, w0.z, acc0.z); acc0.w = fmaf(xa.x, w0.w, acc0.w);
        acc0.x = fmaf(xa.y, w1.x, acc0.x); acc0.y = fmaf(xa.y, w1.y, acc0.y);
        acc0.z = fmaf(xa.y, w1.z, acc0.z); acc0.w = fmaf(xa.y, w1.w, acc0.w);
        acc0.x = fmaf(xa.z, w2.x, acc0.x); acc0.y = fmaf(xa.z, w2.y, acc0.y);
        acc0.z = fmaf(xa.z, w2.z, acc0.z); acc0.w = fmaf(xa.z, w2.w, acc0.w);
        acc0.x = fmaf(xa.w, w3.x, acc0.x); acc0.y = fmaf(xa.w, w3.y, acc0.y);
        acc0.z = fmaf(xa.w, w3.z, acc0.z); acc0.w = fmaf(xa.w, w3.w, acc0.w);
        acc1.x = fmaf(xb.x, w0.x, acc1.x); acc1.y = fmaf(xb.x, w0.y, acc1.y);
        acc1.z = fmaf(xb.x, w0.z, acc1.z); acc1.w = fmaf(xb.x, w0.w, acc1.w);
        acc1.x = fmaf(xb.y, w1.x, acc1.x); acc1.y = fmaf(xb.y, w1.y, acc1.y);
        acc1.z = fmaf(xb.y, w1.z, acc1.z); acc1.w = fmaf(xb.y, w1.w, acc1.w);
        acc1.x = fmaf(xb.z, w2.x, acc1.x); acc1.y = fmaf(xb.z, w2.y, acc1.y);
        acc1.z = fmaf(xb.z, w2.z, acc1.z); acc1.w = fmaf(xb.z, w2.w, acc1.w);
        acc1.x = fmaf(xb.w, w3.x, acc1.x); acc1.y = fmaf(xb.w, w3.y, acc1.y);
        acc1.z = fmaf(xb.w, w3.z, acc1.z); acc1.w = fmaf(xb.w, w3.w, acc1.w);
    }

    float4 bo = make_float4(0.f, 0.f, 0.f, 0.f);
    if (OUT_BIAS_RELU) bo = reinterpret_cast<const float4*>(b_out)[tj];

    if (r0 < N) {
        float4 o = acc0;
        if (OUT_BIAS_RELU) {
            o.x = fmaxf(o.x + bo.x, 0.f); o.y = fmaxf(o.y + bo.y, 0.f);
            o.z = fmaxf(o.z + bo.z, 0.f); o.w = fmaxf(o.w + bo.w, 0.f);
        }
        if (OUT_SCALE) {
            float dv = dinv[r0];
            o.x *= dv; o.y *= dv; o.z *= dv; o.w *= dv;
        }
        *reinterpret_cast<float4*>(out + (size_t)r0 * Fout + (size_t)tj * 4) = o;
    }
    if (r1 < N) {
        float4 o = acc1;
        if (OUT_BIAS_RELU) {
            o.x = fmaxf(o.x + bo.x, 0.f); o.y = fmaxf(o.y + bo.y, 0.f);
            o.z = fmaxf(o.z + bo.z, 0.f); o.w = fmaxf(o.w + bo.w, 0.f);
        }
        if (OUT_SCALE) {
            float dv = dinv[r1];
            o.x *= dv; o.y *= dv; o.z *= dv; o.w *= dv;
        }
        *reinterpret_cast<float4*>(out + (size_t)r1 * Fout + (size_t)tj * 4) = o;
    }
}

// ---------------------------------------------------------------------------
// CSR gather: agg[r] = hs[r] + sum_{j in row r} hs[csr[j]]
// EPI: layer-1 epilogue  out = dinv[r] * relu(dinv[r]*acc + b[k])
// ---------------------------------------------------------------------------
template <int F, bool EPI>
__global__ void gather_kernel(const int* __restrict__ rowptr,
                              const int* __restrict__ csr,
                              const float* __restrict__ hs,
                              const float* __restrict__ b,
                              const float* __restrict__ dinv,
                              float* __restrict__ agg, int N) {
    constexpr int LPR = F / 4;        // lanes per row
    constexpr int RPB = 256 / LPR;    // rows per block
    const int tid = threadIdx.x;
    const int c    = tid % LPR;
    const int rloc = tid / LPR;
    const int r = blockIdx.x * RPB + rloc;
    if (r >= N) return;

    const float4* hs4 = reinterpret_cast<const float4*>(hs);
    float4 acc = hs4[(size_t)r * LPR + c];  // self-loop term

    const int beg = rowptr[r];
    const int end = rowptr[r + 1];
    int j = beg;
    for (; j + 4 <= end; j += 4) {
        int s0 = csr[j], s1 = csr[j + 1], s2 = csr[j + 2], s3 = csr[j + 3];
        float4 v0 = hs4[(size_t)s0 * LPR + c];
        float4 v1 = hs4[(size_t)s1 * LPR + c];
        float4 v2 = hs4[(size_t)s2 * LPR + c];
        float4 v3 = hs4[(size_t)s3 * LPR + c];
        acc.x += v0.x + v1.x + v2.x + v3.x;
        acc.y += v0.y + v1.y + v2.y + v3.y;
        acc.z += v0.z + v1.z + v2.z + v3.z;
        acc.w += v0.w + v1.w + v2.w + v3.w;
    }
    for (; j < end; j++) {
        int s = csr[j];
        float4 v = hs4[(size_t)s * LPR + c];
        acc.x += v.x; acc.y += v.y; acc.z += v.z; acc.w += v.w;
    }
    if (EPI) {
        float dv = dinv[r];
        float4 bb = reinterpret_cast<const float4*>(b)[c];
        acc.x = dv * fmaxf(fmaf(dv, acc.x, bb.x), 0.f);
        acc.y = dv * fmaxf(fmaf(dv, acc.y, bb.y), 0.f);
        acc.z = dv * fmaxf(fmaf(dv, acc.z, bb.z), 0.f);
        acc.w = dv * fmaxf(fmaf(dv, acc.w, bb.w), 0.f);
    }
    reinterpret_cast<float4*>(agg)[(size_t)r * LPR + c] = acc;
}

// ---------------------------------------------------------------------------
// MLP head: reads x4 (already relu'd, unscaled); t = relu(x4@Wf1+bf1);
// out = tanh(t@Wf2+bf2)
// ---------------------------------------------------------------------------
__global__ void head_kernel(const float* __restrict__ x4,
                            const float* __restrict__ Wf1,
                            const float* __restrict__ bf1,
                            const float* __restrict__ Wf2,
                            const float* __restrict__ bf2,
                            float* __restrict__ out, int N) {
    __shared__ float W1s[128 * 32];
    __shared__ float W2s[32 * 10];
    __shared__ float b1s[32], b2s[10];
    __shared__ float xs[8][128];
    __shared__ float ts[8][32];

    const int tid  = threadIdx.x;
    const int lane = tid & 31;
    const int w    = tid >> 5;

    for (int i = tid; i < 128 * 32; i += 256) W1s[i] = Wf1[i];
    for (int i = tid; i < 32 * 10;  i += 256) W2s[i] = Wf2[i];
    if (tid < 32)  b1s[tid] = bf1[tid];
    if (tid < 10)  b2s[tid] = bf2[tid];
    __syncthreads();

    const int r = blockIdx.x * 8 + w;
    if (r >= N) return;

    for (int k = lane; k < 128; k += 32)
        xs[w][k] = x4[(size_t)r * 128 + k];
    __syncwarp();

    float t = b1s[lane];
#pragma unroll 8
    for (int k = 0; k < 128; k++)
        t = fmaf(xs[w][k], W1s[k * 32 + lane], t);
    ts[w][lane] = fmaxf(t, 0.f);
    __syncwarp();

    if (lane < 10) {
        float o = b2s[lane];
#pragma unroll
        for (int j = 0; j < 32; j++)
            o = fmaf(ts[w][j], W2s[j * 10 + lane], o);
        out[(size_t)r * 10 + lane] = tanhf(o);
    }
}

// ---------------------------------------------------------------------------
// Launch
// ---------------------------------------------------------------------------
static inline int cdiv(long long a, long long b) { return (int)((a + b - 1) / b); }

extern "C" void kernel_launch(void* const* d_in, const int* in_sizes, int n_in,
                              void* d_out, int out_size) {
    const float* x  = (const float*)d_in[0];
    const int*   ei = (const int*)d_in[1];       // int64 in reference, delivered as int32
    const float *W1 = (const float*)d_in[2],  *b1 = (const float*)d_in[3];
    const float *W2 = (const float*)d_in[4],  *b2 = (const float*)d_in[5];
    const float *W3 = (const float*)d_in[6],  *b3 = (const float*)d_in[7];
    const float *W4 = (const float*)d_in[8],  *b4 = (const float*)d_in[9];
    const float *Wf1 = (const float*)d_in[10], *bf1 = (const float*)d_in[11];
    const float *Wf2 = (const float*)d_in[12], *bf2 = (const float*)d_in[13];
    float* out = (float*)d_out;

    const int       N = in_sizes[0] / 128;
    const long long E = in_sizes[1] / 2;

    float *hs, *aggA, *aggB, *dinv;
    int *deg, *cur, *rowptr, *csr, *bsum;
    cudaGetSymbolAddress((void**)&hs,     g_hs);
    cudaGetSymbolAddress((void**)&aggA,   g_aggA);
    cudaGetSymbolAddress((void**)&aggB,   g_aggB);
    cudaGetSymbolAddress((void**)&dinv,   g_dinv);
    cudaGetSymbolAddress((void**)&deg,    g_deg);
    cudaGetSymbolAddress((void**)&cur,    g_cur);
    cudaGetSymbolAddress((void**)&rowptr, g_rowptr);
    cudaGetSymbolAddress((void**)&csr,    g_csr);
    cudaGetSymbolAddress((void**)&bsum,   g_bsum);

    const int NB = (N + SCAN_B - 1) / SCAN_B;

    // degree + normalization + CSR build (graph is static across layers)
    zero_deg_kernel<<<cdiv(N, 256), 256>>>(deg, N);
    count_deg_kernel<<<cdiv(E, 256), 256>>>(ei, deg, E);
    dinv_kernel<<<cdiv(N, 256), 256>>>(deg, dinv, cur, N);
    scan_phase1_kernel<<<NB, SCAN_B>>>(deg, bsum, N);
    scan_phase2_kernel<<<1, 512>>>(bsum, NB);
    scan_phase3_kernel<<<NB, SCAN_B>>>(deg, bsum, rowptr, N);
    fill_csr_kernel<<<cdiv(E, 256), 256>>>(ei, rowptr, cur, csr, E);

    // L1 (128->16, propagate-after):
    //   hs = (x @ W1) * dinv
    gemm_kernel<128, 16, 128, false, false, true><<<cdiv(N, 64), 128>>>(
        x, W1, nullptr, dinv, hs, N);
    //   u1 = dinv * relu(dinv * ((A+I) hs) + b1)    [F=16, epilogue gather]
    gather_kernel<16, true><<<cdiv(N, 64), 256>>>(rowptr, csr, hs, b1, dinv, aggA, N);

    // L2 (16->32, propagate-before):
    //   a1 = (A+I) u1                               [F=16]
    gather_kernel<16, false><<<cdiv(N, 64), 256>>>(rowptr, csr, aggA, nullptr, dinv, aggB, N);
    //   u2 = dinv * relu((dinv*a1) @ W2 + b2)
    gemm_kernel<16, 32, 256, true, true, true><<<cdiv(N, 64), 256>>>(
        aggB, W2, b2, dinv, hs, N);

    // L3 (32->64, propagate-before):
    gather_kernel<32, false><<<cdiv(N, 32), 256>>>(rowptr, csr, hs, nullptr, dinv, aggA, N);
    gemm_kernel<32, 64, 256, true, true, true><<<cdiv(N, 32), 256>>>(
        aggA, W3, b3, dinv, aggB, N);

    // L4 (64->128, propagate-before):
    gather_kernel<64, false><<<cdiv(N, 16), 256>>>(rowptr, csr, aggB, nullptr, dinv, hs, N);
    //   x4 = relu((dinv*a3) @ W4 + b4)   (no out-scale; head consumes x4)
    gemm_kernel<64, 128, 256, true, true, false><<<cdiv(N, 16), 256>>>(
        hs, W4, b4, dinv, aggA, N);

    // Head: MLP 128->32->10, tanh
    head_kernel<<<cdiv(N, 8), 256>>>(aggA, Wf1, bf1, Wf2, bf2, out, N);
}

// round 9
// speedup vs baseline: 2.7682x; 1.0488x over previous
#include <cuda_runtime.h>
#include <cuda_bf16.h>
#include <math.h>

#define N_NODES 100000
#define FMAX 128
#define E_MAX 1700000
#define SCAN_B 256
#define SCAN_NB ((N_NODES + SCAN_B - 1) / SCAN_B)   // 391

// Scratch (static __device__ arrays — no allocation allowed)
__device__ float g_hs  [(size_t)N_NODES * FMAX];
__device__ float g_u   [(size_t)N_NODES * FMAX];
__device__ float g_dinv[N_NODES];
__device__ int   g_deg [N_NODES];
__device__ int   g_cur [N_NODES];
__device__ int   g_rowptr[N_NODES + 1];
__device__ int   g_csr [E_MAX];
__device__ int   g_bsum[SCAN_NB];

// ---------------------------------------------------------------------------
// Setup
// ---------------------------------------------------------------------------
__global__ void zero_deg_kernel(int* __restrict__ deg, int n) {
    int i = blockIdx.x * blockDim.x + threadIdx.x;
    if (i < n) deg[i] = 0;
}

__global__ void count_deg_kernel(const int* __restrict__ ei,
                                 int* __restrict__ deg, long long E) {
    long long i = (long long)blockIdx.x * blockDim.x + threadIdx.x;
    if (i < E) atomicAdd(&deg[ei[E + i]], 1);
}

// phase1 also produces dinv and zeroes cur (folds dinv_kernel)
__global__ void scan_phase1_kernel(const int* __restrict__ deg,
                                   int* __restrict__ bsum,
                                   float* __restrict__ dinv,
                                   int* __restrict__ cur, int N) {
    __shared__ int red[SCAN_B];
    const int tid = threadIdx.x;
    const int i = blockIdx.x * SCAN_B + tid;
    int v = (i < N) ? deg[i] : 0;
    if (i < N) {
        dinv[i] = rsqrtf((float)v + 1.0f);
        cur[i] = 0;
    }
    red[tid] = v;
    __syncthreads();
    for (int off = SCAN_B / 2; off > 0; off >>= 1) {
        if (tid < off) red[tid] += red[tid + off];
        __syncthreads();
    }
    if (tid == 0) bsum[blockIdx.x] = red[0];
}

__global__ void scan_phase2_kernel(int* __restrict__ bsum, int NB) {
    __shared__ int s[512];
    const int tid = threadIdx.x;
    int v = (tid < NB) ? bsum[tid] : 0;
    s[tid] = v;
    __syncthreads();
    for (int off = 1; off < 512; off <<= 1) {
        int t = (tid >= off) ? s[tid - off] : 0;
        __syncthreads();
        s[tid] += t;
        __syncthreads();
    }
    if (tid < NB) bsum[tid] = s[tid] - v;   // exclusive
}

__global__ void scan_phase3_kernel(const int* __restrict__ deg,
                                   const int* __restrict__ bsum,
                                   int* __restrict__ rowptr, int N) {
    __shared__ int s[SCAN_B];
    const int tid = threadIdx.x;
    const int i = blockIdx.x * SCAN_B + tid;
    int v = (i < N) ? deg[i] : 0;
    s[tid] = v;
    __syncthreads();
    for (int off = 1; off < SCAN_B; off <<= 1) {
        int t = (tid >= off) ? s[tid - off] : 0;
        __syncthreads();
        s[tid] += t;
        __syncthreads();
    }
    int excl = bsum[blockIdx.x] + s[tid] - v;
    if (i < N) {
        rowptr[i] = excl;
        if (i == N - 1) rowptr[N] = excl + v;
    }
}

__global__ void fill_csr_kernel(const int* __restrict__ ei,
                                const int* __restrict__ rowptr,
                                int* __restrict__ cur,
                                int* __restrict__ csr, long long E) {
    long long e = (long long)blockIdx.x * blockDim.x + threadIdx.x;
    if (e >= E) return;
    int s = ei[e];
    int d = ei[E + e];
    int pos = atomicAdd(&cur[d], 1);
    csr[rowptr[d] + pos] = s;
}

// ---------------------------------------------------------------------------
// Gather helper: acc = u[r] + sum_neighbors u[csr[j]]   (float4 chunk c)
// 8-wide unroll for MLP.
// ---------------------------------------------------------------------------
template <int LPR>
__device__ __forceinline__ float4 gather_row(const float4* __restrict__ u4,
                                             const int* __restrict__ rowptr,
                                             const int* __restrict__ csr,
                                             int r, int c) {
    float4 acc = u4[(size_t)r * LPR + c];  // self-loop
    const int beg = rowptr[r];
    const int end = rowptr[r + 1];
    int j = beg;
    for (; j + 8 <= end; j += 8) {
        int s0 = csr[j],     s1 = csr[j + 1], s2 = csr[j + 2], s3 = csr[j + 3];
        int s4 = csr[j + 4], s5 = csr[j + 5], s6 = csr[j + 6], s7 = csr[j + 7];
        float4 v0 = u4[(size_t)s0 * LPR + c];
        float4 v1 = u4[(size_t)s1 * LPR + c];
        float4 v2 = u4[(size_t)s2 * LPR + c];
        float4 v3 = u4[(size_t)s3 * LPR + c];
        float4 v4 = u4[(size_t)s4 * LPR + c];
        float4 v5 = u4[(size_t)s5 * LPR + c];
        float4 v6 = u4[(size_t)s6 * LPR + c];
        float4 v7 = u4[(size_t)s7 * LPR + c];
        acc.x += (v0.x + v1.x) + (v2.x + v3.x) + (v4.x + v5.x) + (v6.x + v7.x);
        acc.y += (v0.y + v1.y) + (v2.y + v3.y) + (v4.y + v5.y) + (v6.y + v7.y);
        acc.z += (v0.z + v1.z) + (v2.z + v3.z) + (v4.z + v5.z) + (v6.z + v7.z);
        acc.w += (v0.w + v1.w) + (v2.w + v3.w) + (v4.w + v5.w) + (v6.w + v7.w);
    }
    for (; j < end; j++) {
        int s = csr[j];
        float4 v = u4[(size_t)s * LPR + c];
        acc.x += v.x; acc.y += v.y; acc.z += v.z; acc.w += v.w;
    }
    return acc;
}

// ---------------------------------------------------------------------------
// L1 GEMM: hs = (x @ W1) * dinv     (128 -> 16)
// ---------------------------------------------------------------------------
template <int Fin, int Fout, int BLOCK>
__global__ void gemm1_kernel(const float* __restrict__ in,
                             const float* __restrict__ W,
                             const float* __restrict__ dinv,
                             float* __restrict__ hs, int N) {
    constexpr int JT     = Fout / 4;
    constexpr int GROUPS = BLOCK / JT;
    constexpr int ROWS   = GROUPS * 2;
    constexpr int XSTR   = Fin + 4;

    __shared__ __align__(16) float Ws[Fin * Fout];
    __shared__ __align__(16) float Xs[ROWS * XSTR];

    const int tid = threadIdx.x;
    for (int i = tid; i < Fin * Fout; i += BLOCK) Ws[i] = W[i];
    __syncthreads();

    const int row0 = blockIdx.x * ROWS;
    for (int i = tid; i < ROWS * Fin; i += BLOCK) {
        int rl = i / Fin, k = i % Fin;
        int r = row0 + rl;
        Xs[rl * XSTR + k] = (r < N) ? in[(size_t)r * Fin + k] : 0.f;
    }
    __syncthreads();

    const int tj = tid % JT;
    const int tg = tid / JT;
    const int r0 = row0 + tg * 2;
    const int r1 = r0 + 1;

    float4 acc0 = make_float4(0.f, 0.f, 0.f, 0.f);
    float4 acc1 = make_float4(0.f, 0.f, 0.f, 0.f);
    const float4* W4 = reinterpret_cast<const float4*>(Ws);
    const float* x0 = &Xs[(tg * 2 + 0) * XSTR];
    const float* x1 = &Xs[(tg * 2 + 1) * XSTR];

#pragma unroll
    for (int k0 = 0; k0 < Fin; k0 += 4) {
        float4 w0 = W4[(k0 + 0) * JT + tj];
        float4 w1 = W4[(k0 + 1) * JT + tj];
        float4 w2 = W4[(k0 + 2) * JT + tj];
        float4 w3 = W4[(k0 + 3) * JT + tj];
        float4 xa = *reinterpret_cast<const float4*>(x0 + k0);
        float4 xb = *reinterpret_cast<const float4*>(x1 + k0);
        acc0.x = fmaf(xa.x, w0.x, acc0.x); acc0.y = fmaf(xa.x, w0.y, acc0.y);
        acc0.z = fmaf(xa.x, w0.z, acc0.z); acc0.w = fmaf(xa.x, w0.w, acc0.w);
        acc0.x = fmaf(xa.y, w1.x, acc0.x); acc0.y = fmaf(xa.y, w1.y, acc0.y);
        acc0.z = fmaf(xa.y, w1.z, acc0.z); acc0.w = fmaf(xa.y, w1.w, acc0.w);
        acc0.x = fmaf(xa.z, w2.x, acc0.x); acc0.y = fmaf(xa.z, w2.y, acc0.y);
        acc0.z = fmaf(xa.z, w2.z, acc0.z); acc0.w = fmaf(xa.z, w2.w, acc0.w);
        acc0.x = fmaf(xa.w, w3.x, acc0.x); acc0.y = fmaf(xa.w, w3.y, acc0.y);
        acc0.z = fmaf(xa.w, w3.z, acc0.z); acc0.w = fmaf(xa.w, w3.w, acc0.w);
        acc1.x = fmaf(xb.x, w0.x, acc1.x); acc1.y = fmaf(xb.x, w0.y, acc1.y);
        acc1.z = fmaf(xb.x, w0.z, acc1.z); acc1.w = fmaf(xb.x, w0.w, acc1.w);
        acc1.x = fmaf(xb.y, w1.x, acc1.x); acc1.y = fmaf(xb.y, w1.y, acc1.y);
        acc1.z = fmaf(xb.y, w1.z, acc1.z); acc1.w = fmaf(xb.y, w1.w, acc1.w);
        acc1.x = fmaf(xb.z, w2.x, acc1.x); acc1.y = fmaf(xb.z, w2.y, acc1.y);
        acc1.z = fmaf(xb.z, w2.z, acc1.z); acc1.w = fmaf(xb.z, w2.w, acc1.w);
        acc1.x = fmaf(xb.w, w3.x, acc1.x); acc1.y = fmaf(xb.w, w3.y, acc1.y);
        acc1.z = fmaf(xb.w, w3.z, acc1.z); acc1.w = fmaf(xb.w, w3.w, acc1.w);
    }

    if (r0 < N) {
        float dv = dinv[r0];
        float4 o = make_float4(acc0.x * dv, acc0.y * dv, acc0.z * dv, acc0.w * dv);
        *reinterpret_cast<float4*>(hs + (size_t)r0 * Fout + (size_t)tj * 4) = o;
    }
    if (r1 < N) {
        float dv = dinv[r1];
        float4 o = make_float4(acc1.x * dv, acc1.y * dv, acc1.z * dv, acc1.w * dv);
        *reinterpret_cast<float4*>(hs + (size_t)r1 * Fout + (size_t)tj * 4) = o;
    }
}

// ---------------------------------------------------------------------------
// L1 epilogue gather: u1 = dinv * relu(dinv * ((A+I) hs) + b1)   [F=16]
// ---------------------------------------------------------------------------
template <int F>
__global__ void gather_epi_kernel(const int* __restrict__ rowptr,
                                  const int* __restrict__ csr,
                                  const float* __restrict__ hs,
                                  const float* __restrict__ b,
                                  const float* __restrict__ dinv,
                                  float* __restrict__ u, int N) {
    constexpr int LPR = F / 4;
    constexpr int RPB = 256 / LPR;
    const int tid = threadIdx.x;
    const int c    = tid % LPR;
    const int rloc = tid / LPR;
    const int r = blockIdx.x * RPB + rloc;
    if (r >= N) return;

    float4 acc = gather_row<LPR>(reinterpret_cast<const float4*>(hs),
                                 rowptr, csr, r, c);
    float dv = dinv[r];
    float4 bb = reinterpret_cast<const float4*>(b)[c];
    acc.x = dv * fmaxf(fmaf(dv, acc.x, bb.x), 0.f);
    acc.y = dv * fmaxf(fmaf(dv, acc.y, bb.y), 0.f);
    acc.z = dv * fmaxf(fmaf(dv, acc.z, bb.z), 0.f);
    acc.w = dv * fmaxf(fmaf(dv, acc.w, bb.w), 0.f);
    reinterpret_cast<float4*>(u)[(size_t)r * LPR + c] = acc;
}

// ---------------------------------------------------------------------------
// Fused gather + GEMM (propagate-before layers):
//   a = (A+I) u_in;  out = relu((dinv*a) @ W + b);  if OUT_SCALE out *= dinv
// Thread geometry: ROWS*(Fin/4) == BLOCK for all three shapes used.
// ---------------------------------------------------------------------------
template <int Fin, int Fout, int BLOCK, bool OUT_SCALE>
__global__ void fused_gather_gemm_kernel(const int* __restrict__ rowptr,
                                         const int* __restrict__ csr,
                                         const float* __restrict__ u_in,
                                         const float* __restrict__ W,
                                         const float* __restrict__ b_out,
                                         const float* __restrict__ dinv,
                                         float* __restrict__ out, int N) {
    constexpr int JT     = Fout / 4;
    constexpr int GROUPS = BLOCK / JT;
    constexpr int ROWS   = GROUPS * 2;
    constexpr int XSTR   = Fin + 4;
    constexpr int LPR    = Fin / 4;
    static_assert(ROWS * LPR == BLOCK, "geometry mismatch");

    __shared__ __align__(16) float Ws[Fin * Fout];
    __shared__ __align__(16) float Xs[ROWS * XSTR];

    const int tid = threadIdx.x;
    for (int i = tid; i < Fin * Fout; i += BLOCK) Ws[i] = W[i];

    // cooperative gather straight into Xs (dinv applied inline)
    const int row0 = blockIdx.x * ROWS;
    {
        const int c  = tid % LPR;
        const int rl = tid / LPR;
        const int r  = row0 + rl;
        float4 acc = make_float4(0.f, 0.f, 0.f, 0.f);
        if (r < N) {
            acc = gather_row<LPR>(reinterpret_cast<const float4*>(u_in),
                                  rowptr, csr, r, c);
            float dv = dinv[r];
            acc.x *= dv; acc.y *= dv; acc.z *= dv; acc.w *= dv;
        }
        *reinterpret_cast<float4*>(&Xs[rl * XSTR + c * 4]) = acc;
    }
    __syncthreads();

    const int tj = tid % JT;
    const int tg = tid / JT;
    const int r0 = row0 + tg * 2;
    const int r1 = r0 + 1;

    float4 acc0 = make_float4(0.f, 0.f, 0.f, 0.f);
    float4 acc1 = make_float4(0.f, 0.f, 0.f, 0.f);
    const float4* W4 = reinterpret_cast<const float4*>(Ws);
    const float* x0 = &Xs[(tg * 2 + 0) * XSTR];
    const float* x1 = &Xs[(tg * 2 + 1) * XSTR];

#pragma unroll
    for (int k0 = 0; k0 < Fin; k0 += 4) {
        float4 w0 = W4[(k0 + 0) * JT + tj];
        float4 w1 = W4[(k0 + 1) * JT + tj];
        float4 w2 = W4[(k0 + 2) * JT + tj];
        float4 w3 = W4[(k0 + 3) * JT + tj];
        float4 xa = *reinterpret_cast<const float4*>(x0 + k0);
        float4 xb = *reinterpret_cast<const float4*>(x1 + k0);
        acc0.x = fmaf(xa.x, w0.x, acc0.x); acc0.y = fmaf(xa.x, w0.y, acc0.y);
        acc0.z = fmaf(xa.x, w0.z, acc0.z); acc0.w = fmaf(xa.x, w0.w, acc0.w);
        acc0.x = fmaf(xa.y, w1.x, acc0.x); acc0.y = fmaf(xa.y, w1.y, acc0.y);
        acc0.z = fmaf(xa.y, w1.z, acc0.z); acc0.w = fmaf(xa.y, w1.w, acc0.w);
        acc0.x = fmaf(xa.z, w2.x, acc0.x); acc0.y = fmaf(xa.z, w2.y, acc0.y);
        acc0.z = fmaf(xa.z, w2.z, acc0.z); acc0.w = fmaf(xa.z, w2.w, acc0.w);
        acc0.x = fmaf(xa.w, w3.x, acc0.x); acc0.y = fmaf(xa.w, w3.y, acc0.y);
        acc0.z = fmaf(xa.w, w3.z, acc0.z); acc0.w = fmaf(xa.w, w3.w, acc0.w);
        acc1.x = fmaf(xb.x, w0.x, acc1.x); acc1.y = fmaf(xb.x, w0.y, acc1.y);
        acc1.z = fmaf(xb.x, w0.z, acc1.z); acc1.w = fmaf(xb.x, w0.w, acc1.w);
        acc1.x = fmaf(xb.y, w1.x, acc1.x); acc1.y = fmaf(xb.y, w1.y, acc1.y);
        acc1.z = fmaf(xb.y, w1.z, acc1.z); acc1.w = fmaf(xb.y, w1.w, acc1.w);
        acc1.x = fmaf(xb.z, w2.x, acc1.x); acc1.y = fmaf(xb.z, w2.y, acc1.y);
        acc1.z = fmaf(xb.z, w2.z, acc1.z); acc1.w = fmaf(xb.z, w2.w, acc1.w);
        acc1.x = fmaf(xb.w, w3.x, acc1.x); acc1.y = fmaf(xb.w, w3.y, acc1.y);
        acc1.z = fmaf(xb.w, w3.z, acc1.z); acc1.w = fmaf(xb.w, w3.w, acc1.w);
    }

    float4 bo = reinterpret_cast<const float4*>(b_out)[tj];

    if (r0 < N) {
        float4 o = acc0;
        o.x = fmaxf(o.x + bo.x, 0.f); o.y = fmaxf(o.y + bo.y, 0.f);
        o.z = fmaxf(o.z + bo.z, 0.f); o.w = fmaxf(o.w + bo.w, 0.f);
        if (OUT_SCALE) {
            float dv = dinv[r0];
            o.x *= dv; o.y *= dv; o.z *= dv; o.w *= dv;
        }
        *reinterpret_cast<float4*>(out + (size_t)r0 * Fout + (size_t)tj * 4) = o;
    }
    if (r1 < N) {
        float4 o = acc1;
        o.x = fmaxf(o.x + bo.x, 0.f); o.y = fmaxf(o.y + bo.y, 0.f);
        o.z = fmaxf(o.z + bo.z, 0.f); o.w = fmaxf(o.w + bo.w, 0.f);
        if (OUT_SCALE) {
            float dv = dinv[r1];
            o.x *= dv; o.y *= dv; o.z *= dv; o.w *= dv;
        }
        *reinterpret_cast<float4*>(out + (size_t)r1 * Fout + (size_t)tj * 4) = o;
    }
}

// ---------------------------------------------------------------------------
// MLP head: t = relu(x4@Wf1+bf1); out = tanh(t@Wf2+bf2)
// ---------------------------------------------------------------------------
__global__ void head_kernel(const float* __restrict__ x4,
                            const float* __restrict__ Wf1,
                            const float* __restrict__ bf1,
                            const float* __restrict__ Wf2,
                            const float* __restrict__ bf2,
                            float* __restrict__ out, int N) {
    __shared__ float W1s[128 * 32];
    __shared__ float W2s[32 * 10];
    __shared__ float b1s[32], b2s[10];
    __shared__ float xs[8][128];
    __shared__ float ts[8][32];

    const int tid  = threadIdx.x;
    const int lane = tid & 31;
    const int w    = tid >> 5;

    for (int i = tid; i < 128 * 32; i += 256) W1s[i] = Wf1[i];
    for (int i = tid; i < 32 * 10;  i += 256) W2s[i] = Wf2[i];
    if (tid < 32)  b1s[tid] = bf1[tid];
    if (tid < 10)  b2s[tid] = bf2[tid];
    __syncthreads();

    const int r = blockIdx.x * 8 + w;
    if (r >= N) return;

    for (int k = lane; k < 128; k += 32)
        xs[w][k] = x4[(size_t)r * 128 + k];
    __syncwarp();

    float t = b1s[lane];
#pragma unroll 8
    for (int k = 0; k < 128; k++)
        t = fmaf(xs[w][k], W1s[k * 32 + lane], t);
    ts[w][lane] = fmaxf(t, 0.f);
    __syncwarp();

    if (lane < 10) {
        float o = b2s[lane];
#pragma unroll
        for (int j = 0; j < 32; j++)
            o = fmaf(ts[w][j], W2s[j * 10 + lane], o);
        out[(size_t)r * 10 + lane] = tanhf(o);
    }
}

// ---------------------------------------------------------------------------
// Launch
// ---------------------------------------------------------------------------
static inline int cdiv(long long a, long long b) { return (int)((a + b - 1) / b); }

extern "C" void kernel_launch(void* const* d_in, const int* in_sizes, int n_in,
                              void* d_out, int out_size) {
    const float* x  = (const float*)d_in[0];
    const int*   ei = (const int*)d_in[1];       // int64 in reference, delivered as int32
    const float *W1 = (const float*)d_in[2],  *b1 = (const float*)d_in[3];
    const float *W2 = (const float*)d_in[4],  *b2 = (const float*)d_in[5];
    const float *W3 = (const float*)d_in[6],  *b3 = (const float*)d_in[7];
    const float *W4 = (const float*)d_in[8],  *b4 = (const float*)d_in[9];
    const float *Wf1 = (const float*)d_in[10], *bf1 = (const float*)d_in[11];
    const float *Wf2 = (const float*)d_in[12], *bf2 = (const float*)d_in[13];
    float* out = (float*)d_out;

    const int       N = in_sizes[0] / 128;
    const long long E = in_sizes[1] / 2;

    float *hs, *u, *dinv;
    int *deg, *cur, *rowptr, *csr, *bsum;
    cudaGetSymbolAddress((void**)&hs,     g_hs);
    cudaGetSymbolAddress((void**)&u,      g_u);
    cudaGetSymbolAddress((void**)&dinv,   g_dinv);
    cudaGetSymbolAddress((void**)&deg,    g_deg);
    cudaGetSymbolAddress((void**)&cur,    g_cur);
    cudaGetSymbolAddress((void**)&rowptr, g_rowptr);
    cudaGetSymbolAddress((void**)&csr,    g_csr);
    cudaGetSymbolAddress((void**)&bsum,   g_bsum);

    const int NB = (N + SCAN_B - 1) / SCAN_B;

    // setup: degree, dinv, rowptr, csr
    zero_deg_kernel<<<cdiv(N, 256), 256>>>(deg, N);
    count_deg_kernel<<<cdiv(E, 256), 256>>>(ei, deg, E);
    scan_phase1_kernel<<<NB, SCAN_B>>>(deg, bsum, dinv, cur, N);
    scan_phase2_kernel<<<1, 512>>>(bsum, NB);
    scan_phase3_kernel<<<NB, SCAN_B>>>(deg, bsum, rowptr, N);
    fill_csr_kernel<<<cdiv(E, 256), 256>>>(ei, rowptr, cur, csr, E);

    // L1 (128->16): hs = (x @ W1) * dinv
    gemm1_kernel<128, 16, 128><<<cdiv(N, 64), 128>>>(x, W1, dinv, hs, N);
    // u1 = dinv * relu(dinv * ((A+I) hs) + b1)
    gather_epi_kernel<16><<<cdiv(N, 64), 256>>>(rowptr, csr, hs, b1, dinv, u, N);

    // L2 (16->32): gather u1, GEMM, emit u2  (ROWS=64)
    fused_gather_gemm_kernel<16, 32, 256, true><<<cdiv(N, 64), 256>>>(
        rowptr, csr, u, W2, b2, dinv, hs, N);

    // L3 (32->64): gather u2, GEMM, emit u3  (ROWS=32)
    fused_gather_gemm_kernel<32, 64, 256, true><<<cdiv(N, 32), 256>>>(
        rowptr, csr, hs, W3, b3, dinv, u, N);

    // L4 (64->128): gather u3, GEMM, emit x4 (no out-scale; ROWS=16)
    fused_gather_gemm_kernel<64, 128, 256, false><<<cdiv(N, 16), 256>>>(
        rowptr, csr, u, W4, b4, dinv, hs, N);

    // Head: MLP 128->32->10, tanh
    head_kernel<<<cdiv(N, 8), 256>>>(hs, Wf1, bf1, Wf2, bf2, out, N);
}